// round 11
// baseline (speedup 1.0000x reference)
#include <cuda_runtime.h>
#include <cuda_bf16.h>
#include <cuda_fp16.h>
#include <cstdint>

// Problem constants
#define N_ENT    100000
#define N_REL    250000
#define N_TRIG   50000
#define N_ARGS   250000
#define ENT_DIM  288
#define REL_R    256
#define RTYPE_DIM 32
#define ROLE_DIM 256
#define ARG_DIM  576
#define KDIM     1152          // 2 * ARG_DIM (in-slot | out-slot)
#define OUT_COLS 544           // ENT_DIM + ROLE_DIM

// Scratch
__device__ __half g_Xh[(size_t)N_TRIG * KDIM];   // 115.2 MB, written once by accum
__device__ __half g_Bth[ROLE_DIM * KDIM];        // W^T [n][k], fp16
__device__ int    g_cnt[N_TRIG];                 // per-trigger arg counts
__device__ int    g_off[N_TRIG];                 // exclusive offsets -> cursors -> ends
__device__ int    g_aux[64];                     // scan block sums
__device__ int    g_auxs[64];                    // scanned block sums
__device__ int    g_list[N_ARGS];                // args sorted by trigger

#define NSCAN 49                                 // ceil(50000/1024)

// ---------------------------------------------------------------------------
// helpers
// ---------------------------------------------------------------------------
__device__ __forceinline__ uint32_t smem_u32(const void* p) {
    uint32_t a;
    asm("{ .reg .u64 t; cvta.to.shared.u64 t, %1; cvt.u32.u64 %0, t; }"
        : "=r"(a) : "l"(p));
    return a;
}

// streaming load (L2 evict_first) of a float4
__device__ __forceinline__ float4 ld4_stream(const float4* p, uint64_t pol) {
    float4 v;
    asm volatile("ld.global.nc.L2::cache_hint.v4.f32 {%0,%1,%2,%3}, [%4], %5;"
                 : "=f"(v.x), "=f"(v.y), "=f"(v.z), "=f"(v.w)
                 : "l"(p), "l"(pol));
    return v;
}

__device__ __forceinline__ void cp16(uint32_t dst, const void* src) {
    asm volatile("cp.async.cg.shared.global [%0], [%1], 16;" :: "r"(dst), "l"(src));
}
__device__ __forceinline__ void cp16_pred(uint32_t dst, const void* src, int bytes) {
    asm volatile("cp.async.cg.shared.global [%0], [%1], 16, %2;"
                 :: "r"(dst), "l"(src), "r"(bytes));
}
__device__ __forceinline__ void cp_commit() {
    asm volatile("cp.async.commit_group;" ::: "memory");
}
template <int N> __device__ __forceinline__ void cp_wait() {
    asm volatile("cp.async.wait_group %0;" :: "n"(N) : "memory");
}

#define MMA_F16(acc, ar, br)                                                    \
    asm volatile(                                                               \
        "mma.sync.aligned.m16n8k16.row.col.f32.f16.f16.f32 "                    \
        "{%0,%1,%2,%3},{%4,%5,%6,%7},{%8,%9},{%0,%1,%2,%3};"                    \
        : "+f"((acc)[0]), "+f"((acc)[1]), "+f"((acc)[2]), "+f"((acc)[3])        \
        : "r"((ar)[0]), "r"((ar)[1]), "r"((ar)[2]), "r"((ar)[3]),               \
          "r"((br)[0]), "r"((br)[1]))

#define LDMATRIX_X4(r, addr)                                                    \
    asm volatile("ldmatrix.sync.aligned.m8n8.x4.shared.b16 {%0,%1,%2,%3}, [%4];"\
                 : "=r"((r)[0]), "=r"((r)[1]), "=r"((r)[2]), "=r"((r)[3])       \
                 : "r"(addr))

// ---------------------------------------------------------------------------
// Fused kernel 1: [bprep | per-trigger count | trig_copy] by block range.
// ---------------------------------------------------------------------------
#define PREP_BPREP 1152                     // (1152*256)/256
#define PREP_CNT   977                      // ceil(250000/256)
#define PREP_TRIG  (N_TRIG / 8)             // 6250, 1 trig per warp
#define PREP_GRID  (PREP_BPREP + PREP_CNT + PREP_TRIG)

__global__ __launch_bounds__(256)
void prep_count_kernel(const float* __restrict__ ent_embeds,
                       const float* __restrict__ Win,
                       const float* __restrict__ Wout,
                       const int*   __restrict__ trig_ent_id,
                       const int*   __restrict__ arg_trig,
                       float* __restrict__ out) {
    int bid = blockIdx.x;
    int tid = threadIdx.x;

    if (bid < PREP_BPREP) {
        int idx = bid * 256 + tid;
        int k = idx / ROLE_DIM;
        int n = idx % ROLE_DIM;
        float v = (k < ARG_DIM) ? Win[k * ROLE_DIM + n]
                                : Wout[(k - ARG_DIM) * ROLE_DIM + n];
        g_Bth[n * KDIM + k] = __float2half_rn(v);
        return;
    }
    bid -= PREP_BPREP;
    if (bid < PREP_CNT) {
        int a = bid * 256 + tid;
        if (a < N_ARGS) atomicAdd(&g_cnt[arg_trig[a]], 1);
        return;
    }
    bid -= PREP_CNT;
    {
        int warp = bid * 8 + (tid >> 5);
        int lane = tid & 31;
        const float4* src = (const float4*)(ent_embeds + (size_t)trig_ent_id[warp] * ENT_DIM);
        float4* dst = (float4*)(out + (size_t)warp * OUT_COLS);
        #pragma unroll
        for (int it = 0; it < 3; ++it) {
            int c = lane + it * 32;
            if (c < ENT_DIM / 4) dst[c] = src[c];
        }
    }
}

// ---------------------------------------------------------------------------
// Two-level exclusive scan of g_cnt -> g_off
// ---------------------------------------------------------------------------
__global__ __launch_bounds__(1024)
void scanA_kernel() {
    __shared__ int s[1024];
    int i = blockIdx.x * 1024 + threadIdx.x;
    int v = (i < N_TRIG) ? g_cnt[i] : 0;
    s[threadIdx.x] = v;
    __syncthreads();
    #pragma unroll
    for (int d = 1; d < 1024; d <<= 1) {
        int t = (threadIdx.x >= d) ? s[threadIdx.x - d] : 0;
        __syncthreads();
        s[threadIdx.x] += t;
        __syncthreads();
    }
    if (i < N_TRIG) g_off[i] = s[threadIdx.x] - v;   // exclusive within block
    if (threadIdx.x == 1023) g_aux[blockIdx.x] = s[1023];
}

__global__ void scanB_kernel() {
    if (threadIdx.x == 0) {
        int run = 0;
        for (int b = 0; b < NSCAN; b++) { g_auxs[b] = run; run += g_aux[b]; }
    }
}

__global__ __launch_bounds__(1024)
void addback_kernel() {
    int i = blockIdx.x * 1024 + threadIdx.x;
    if (i < N_TRIG) g_off[i] += g_auxs[blockIdx.x];
}

// ---------------------------------------------------------------------------
// Fill: bucket args by trigger. g_off becomes bucket END after this.
// ---------------------------------------------------------------------------
__global__ __launch_bounds__(256)
void fill_kernel(const int* __restrict__ arg_trig) {
    int a = blockIdx.x * 256 + threadIdx.x;
    if (a < N_ARGS) {
        int pos = atomicAdd(&g_off[arg_trig[a]], 1);
        g_list[pos] = a;
    }
}

// ---------------------------------------------------------------------------
// Accumulate: one warp per trigger. fp32 register accumulation of
// x = sum [rel|rtype|ent] per slot, single fp16 write of X row.
// Lane owns chunk c = it*32+lane (8 floats each), it = 0..2, c < 72.
// ---------------------------------------------------------------------------
__global__ __launch_bounds__(256)
void accum_kernel(const float* __restrict__ rel_embeds,
                  const float* __restrict__ rtype_table,
                  const float* __restrict__ ent_embeds,
                  const int*   __restrict__ rtype_ids,
                  const int*   __restrict__ arg_rel,
                  const int*   __restrict__ arg_ent,
                  const int*   __restrict__ arg_is_in) {
    int w = blockIdx.x * 8 + (threadIdx.x >> 5);
    int lane = threadIdx.x & 31;
    if (w >= N_TRIG) return;

    int start = (w == 0) ? 0 : g_off[w - 1];
    int end = g_off[w];

    uint64_t pol;
    asm("createpolicy.fractional.L2::evict_first.b64 %0, 1.0;" : "=l"(pol));

    float accA[3][8], accB[3][8];     // in-slot, out-slot
    #pragma unroll
    for (int it = 0; it < 3; it++)
        #pragma unroll
        for (int j = 0; j < 8; j++) { accA[it][j] = 0.f; accB[it][j] = 0.f; }

    for (int a = start; a < end; a++) {
        int idx = g_list[a];
        int r = arg_rel[idx];
        int e = arg_ent[idx];
        int m = arg_is_in[idx];
        int rt = rtype_ids[r];

        const float4* relv = (const float4*)(rel_embeds  + (size_t)r  * REL_R);
        const float4* rtv  = (const float4*)(rtype_table + (size_t)rt * RTYPE_DIM);
        const float4* entv = (const float4*)(ent_embeds  + (size_t)e  * ENT_DIM);

        float4 v[3][2];
        // it 0: chunks 0..31 -> rel (stream)
        v[0][0] = ld4_stream(relv + lane * 2, pol);
        v[0][1] = ld4_stream(relv + lane * 2 + 1, pol);
        // it 1: chunks 32..63 -> lanes 0-3 rtype, lanes 4-31 ent chunks 0..27
        if (lane < 4) { v[1][0] = rtv[lane * 2];         v[1][1] = rtv[lane * 2 + 1]; }
        else          { v[1][0] = entv[(lane - 4) * 2];  v[1][1] = entv[(lane - 4) * 2 + 1]; }
        // it 2: chunks 64..71 -> lanes 0-7 ent chunks 28..35
        if (lane < 8) { v[2][0] = entv[(lane + 28) * 2]; v[2][1] = entv[(lane + 28) * 2 + 1]; }
        else          { v[2][0] = make_float4(0,0,0,0);  v[2][1] = make_float4(0,0,0,0); }

        if (m) {
            #pragma unroll
            for (int it = 0; it < 3; it++) {
                accA[it][0] += v[it][0].x; accA[it][1] += v[it][0].y;
                accA[it][2] += v[it][0].z; accA[it][3] += v[it][0].w;
                accA[it][4] += v[it][1].x; accA[it][5] += v[it][1].y;
                accA[it][6] += v[it][1].z; accA[it][7] += v[it][1].w;
            }
        } else {
            #pragma unroll
            for (int it = 0; it < 3; it++) {
                accB[it][0] += v[it][0].x; accB[it][1] += v[it][0].y;
                accB[it][2] += v[it][0].z; accB[it][3] += v[it][0].w;
                accB[it][4] += v[it][1].x; accB[it][5] += v[it][1].y;
                accB[it][6] += v[it][1].z; accB[it][7] += v[it][1].w;
            }
        }
    }

    // write X row (both slots), one 16B store per valid chunk
    __half* row = g_Xh + (size_t)w * KDIM;
    #pragma unroll
    for (int it = 0; it < 3; it++) {
        int c = it * 32 + lane;
        if (c < 72) {
            __half2 h[4];
            h[0] = __floats2half2_rn(accA[it][0], accA[it][1]);
            h[1] = __floats2half2_rn(accA[it][2], accA[it][3]);
            h[2] = __floats2half2_rn(accA[it][4], accA[it][5]);
            h[3] = __floats2half2_rn(accA[it][6], accA[it][7]);
            *(uint4*)(row + c * 8) = *(uint4*)h;
            h[0] = __floats2half2_rn(accB[it][0], accB[it][1]);
            h[1] = __floats2half2_rn(accB[it][2], accB[it][3]);
            h[2] = __floats2half2_rn(accB[it][4], accB[it][5]);
            h[3] = __floats2half2_rn(accB[it][6], accB[it][7]);
            *(uint4*)(row + ARG_DIM + c * 8) = *(uint4*)h;
        }
    }
}

// ---------------------------------------------------------------------------
// mma.sync fp16 GEMM: out[:,288:544] = Xh[50000,1152] @ Wcat  (unchanged R9)
// ---------------------------------------------------------------------------
#define CHUNK  64
#define NCH    (KDIM / CHUNK)         // 18
#define ROWB   144
#define OFF_B  (128 * ROWB)           // 18432
#define STG_STRIDE (2 * 128 * ROWB)   // 36864
#define NSTAGE 3
#define GSMEM  (NSTAGE * STG_STRIDE)  // 110592

__global__ __launch_bounds__(128, 2)
void gemm_mma_kernel(float* __restrict__ out) {
    extern __shared__ char sm[];
    const uint32_t smb = smem_u32(sm);
    const int tid = threadIdx.x;
    const int lid = tid & 31;
    const int wid = tid >> 5;
    const int m0 = blockIdx.y * 128;
    const int n0 = blockIdx.x * 128;
    const int wm = (wid >> 1) * 64;
    const int wn = (wid & 1) * 64;
    const int g  = lid >> 2;
    const int kp = (lid & 3) * 2;

    float acc[4][8][4];
    #pragma unroll
    for (int a = 0; a < 4; a++)
        #pragma unroll
        for (int b = 0; b < 8; b++)
            #pragma unroll
            for (int c = 0; c < 4; c++) acc[a][b][c] = 0.f;

    auto cpStage = [&](int c, int p) {
        uint32_t stg = smb + p * STG_STRIDE;
        #pragma unroll
        for (int u = 0; u < 8; u++) {
            int idx = u * 128 + tid;
            int row = idx >> 3, seg = idx & 7;
            int gm = m0 + row;
            const __half* sa = g_Xh + (size_t)gm * KDIM + c * CHUNK + seg * 8;
            cp16_pred(stg + row * ROWB + seg * 16, sa, (gm < N_TRIG) ? 16 : 0);
            const __half* sb = g_Bth + (size_t)(n0 + row) * KDIM + c * CHUNK + seg * 8;
            cp16(stg + OFF_B + row * ROWB + seg * 16, sb);
        }
        cp_commit();
    };

    auto compute = [&](int p) {
        const uint32_t base = smb + p * STG_STRIDE;
        #pragma unroll
        for (int ks = 0; ks < 4; ks++) {
            uint32_t a[4][4], b[4][4];
            {
                uint32_t addr = base + OFF_B + (uint32_t)(wn + (lid & 15)) * ROWB
                              + ks * 32 + (lid >> 4) * 16;
                LDMATRIX_X4(b[0], addr);
            }
            #pragma unroll
            for (int mf = 0; mf < 4; mf++) {
                uint32_t addr = base + (uint32_t)(wm + mf * 16 + (lid & 15)) * ROWB
                              + ks * 32 + (lid >> 4) * 16;
                LDMATRIX_X4(a[mf], addr);
            }
            #pragma unroll
            for (int np = 0; np < 4; np++) {
                if (np < 3) {
                    uint32_t addr = base + OFF_B
                                  + (uint32_t)(wn + (np + 1) * 16 + (lid & 15)) * ROWB
                                  + ks * 32 + (lid >> 4) * 16;
                    LDMATRIX_X4(b[np + 1], addr);
                }
                uint32_t blo[2] = { b[np][0], b[np][2] };
                uint32_t bhi[2] = { b[np][1], b[np][3] };
                #pragma unroll
                for (int mf = 0; mf < 4; mf++) {
                    MMA_F16(acc[mf][2 * np],     a[mf], blo);
                    MMA_F16(acc[mf][2 * np + 1], a[mf], bhi);
                }
            }
        }
    };

    cpStage(0, 0);
    cpStage(1, 1);

    for (int i = 0; i < NCH; i++) {
        cp_wait<1>();
        __syncthreads();
        if (i + 2 < NCH) cpStage(i + 2, (i + 2) % NSTAGE);
        else             cp_commit();
        compute(i % NSTAGE);
    }

    #pragma unroll
    for (int mf = 0; mf < 4; mf++) {
        int r = m0 + wm + mf * 16 + g;
        #pragma unroll
        for (int nf = 0; nf < 8; nf++) {
            int cc = ENT_DIM + n0 + wn + nf * 8 + kp;
            if (r < N_TRIG)
                *(float2*)(out + (size_t)r * OUT_COLS + cc) =
                    make_float2(acc[mf][nf][0], acc[mf][nf][1]);
            if (r + 8 < N_TRIG)
                *(float2*)(out + (size_t)(r + 8) * OUT_COLS + cc) =
                    make_float2(acc[mf][nf][2], acc[mf][nf][3]);
        }
    }
}

// ---------------------------------------------------------------------------
// Launch
// ---------------------------------------------------------------------------
extern "C" void kernel_launch(void* const* d_in, const int* in_sizes, int n_in,
                              void* d_out, int out_size) {
    const float* ent_embeds  = (const float*)d_in[0];
    const float* rel_embeds  = (const float*)d_in[1];
    const float* rtype_table = (const float*)d_in[2];
    const float* W_in        = (const float*)d_in[3];
    const float* W_out       = (const float*)d_in[4];
    const int*   rtype_ids   = (const int*)d_in[5];
    const int*   trig_ent_id = (const int*)d_in[6];
    const int*   arg_trig    = (const int*)d_in[7];
    const int*   arg_rel     = (const int*)d_in[8];
    const int*   arg_ent     = (const int*)d_in[9];
    const int*   arg_is_in   = (const int*)d_in[10];
    float* out = (float*)d_out;

    cudaFuncSetAttribute(gemm_mma_kernel,
                         cudaFuncAttributeMaxDynamicSharedMemorySize, GSMEM);

    // zero per-trigger counters (200 KB; X no longer needs zeroing)
    void* cptr = nullptr;
    cudaGetSymbolAddress(&cptr, g_cnt);
    cudaMemsetAsync(cptr, 0, N_TRIG * sizeof(int), 0);

    // fused: W transpose + arg count + trigger-embedding copy
    prep_count_kernel<<<PREP_GRID, 256>>>(ent_embeds, W_in, W_out,
                                          trig_ent_id, arg_trig, out);

    // exclusive scan of counts -> g_off
    scanA_kernel<<<NSCAN, 1024>>>();
    scanB_kernel<<<1, 64>>>();
    addback_kernel<<<NSCAN, 1024>>>();

    // bucket args by trigger
    fill_kernel<<<PREP_CNT, 256>>>(arg_trig);

    // per-trigger fp32 accumulate + single fp16 X write
    accum_kernel<<<N_TRIG / 8, 256>>>(rel_embeds, rtype_table, ent_embeds,
                                      rtype_ids, arg_rel, arg_ent, arg_is_in);

    // tensor-core GEMM -> out[:, 288:544]
    dim3 grid(ROLE_DIM / 128, (N_TRIG + 127) / 128);
    gemm_mma_kernel<<<grid, 128, GSMEM>>>(out);
}

// round 12
// speedup vs baseline: 1.4808x; 1.4808x over previous
#include <cuda_runtime.h>
#include <cuda_bf16.h>
#include <cuda_fp16.h>
#include <cstdint>

// Problem constants
#define N_ENT    100000
#define N_REL    250000
#define N_TRIG   50000
#define N_ARGS   250000
#define ENT_DIM  288
#define REL_R    256
#define RTYPE_DIM 32
#define ROLE_DIM 256
#define ARG_DIM  576
#define KDIM     1152          // 2 * ARG_DIM (in-slot | out-slot)
#define OUT_COLS 544           // ENT_DIM + ROLE_DIM

// Scratch (fp16 X accumulators + fp16 W^T)
__device__ __half g_Xh[(size_t)N_TRIG * KDIM];   // 115.2 MB
__device__ __half g_Bth[ROLE_DIM * KDIM];        // W^T [n][k], fp16

// ---------------------------------------------------------------------------
// helpers
// ---------------------------------------------------------------------------
__device__ __forceinline__ uint32_t smem_u32(const void* p) {
    uint32_t a;
    asm("{ .reg .u64 t; cvta.to.shared.u64 t, %1; cvt.u32.u64 %0, t; }"
        : "=r"(a) : "l"(p));
    return a;
}

__device__ __forceinline__ void red_h8(__half* p, uint32_t a, uint32_t b,
                                       uint32_t c, uint32_t d) {
    asm volatile("red.global.add.noftz.v4.f16x2 [%0], {%1,%2,%3,%4};"
                 :: "l"(p), "r"(a), "r"(b), "r"(c), "r"(d) : "memory");
}

// streaming load (L2 evict_first) of a float4
__device__ __forceinline__ float4 ld4_stream(const float4* p, uint64_t pol) {
    float4 v;
    asm volatile("ld.global.nc.L2::cache_hint.v4.f32 {%0,%1,%2,%3}, [%4], %5;"
                 : "=f"(v.x), "=f"(v.y), "=f"(v.z), "=f"(v.w)
                 : "l"(p), "l"(pol));
    return v;
}

__device__ __forceinline__ void cp16(uint32_t dst, const void* src) {
    asm volatile("cp.async.cg.shared.global [%0], [%1], 16;" :: "r"(dst), "l"(src));
}
__device__ __forceinline__ void cp16_pred(uint32_t dst, const void* src, int bytes) {
    asm volatile("cp.async.cg.shared.global [%0], [%1], 16, %2;"
                 :: "r"(dst), "l"(src), "r"(bytes));
}
__device__ __forceinline__ void cp_commit() {
    asm volatile("cp.async.commit_group;" ::: "memory");
}
template <int N> __device__ __forceinline__ void cp_wait() {
    asm volatile("cp.async.wait_group %0;" :: "n"(N) : "memory");
}

#define MMA_F16(acc, ar, br)                                                    \
    asm volatile(                                                               \
        "mma.sync.aligned.m16n8k16.row.col.f32.f16.f16.f32 "                    \
        "{%0,%1,%2,%3},{%4,%5,%6,%7},{%8,%9},{%0,%1,%2,%3};"                    \
        : "+f"((acc)[0]), "+f"((acc)[1]), "+f"((acc)[2]), "+f"((acc)[3])        \
        : "r"((ar)[0]), "r"((ar)[1]), "r"((ar)[2]), "r"((ar)[3]),               \
          "r"((br)[0]), "r"((br)[1]))

#define LDMATRIX_X4(r, addr)                                                    \
    asm volatile("ldmatrix.sync.aligned.m8n8.x4.shared.b16 {%0,%1,%2,%3}, [%4];"\
                 : "=r"((r)[0]), "=r"((r)[1]), "=r"((r)[2]), "=r"((r)[3])       \
                 : "r"(addr))

// ---------------------------------------------------------------------------
// Fused prep kernel: [bprep | scatter (2 args/warp) | trig_copy] by block range.
// ---------------------------------------------------------------------------
#define PREP_BPREP 1152                     // (1152*256 elems)/256 thr
#define PREP_SCAT  (N_ARGS / 16)            // 15625 blocks, 2 args per warp
#define PREP_TRIG  (N_TRIG / 8)             // 6250, 1 trig per warp
#define PREP_GRID  (PREP_BPREP + PREP_SCAT + PREP_TRIG)

__global__ __launch_bounds__(256)
void prep_kernel(const float* __restrict__ ent_embeds,
                 const float* __restrict__ rel_embeds,
                 const float* __restrict__ rtype_table,
                 const float* __restrict__ Win,
                 const float* __restrict__ Wout,
                 const int*   __restrict__ rtype_ids,
                 const int*   __restrict__ trig_ent_id,
                 const int*   __restrict__ arg_trig,
                 const int*   __restrict__ arg_rel,
                 const int*   __restrict__ arg_ent,
                 const int*   __restrict__ arg_is_in,
                 float* __restrict__ out) {
    int bid = blockIdx.x;
    int tid = threadIdx.x;
    int lane = tid & 31;
    int wip = tid >> 5;

    if (bid < PREP_BPREP) {
        int idx = bid * 256 + tid;
        int k = idx / ROLE_DIM;
        int n = idx % ROLE_DIM;
        float v = (k < ARG_DIM) ? Win[k * ROLE_DIM + n]
                                : Wout[(k - ARG_DIM) * ROLE_DIM + n];
        g_Bth[n * KDIM + k] = __float2half_rn(v);
        return;
    }
    bid -= PREP_BPREP;
    if (bid < PREP_SCAT) {
        // ---- scatter: one warp per TWO args (interleaved for 2x MLP) ----
        int pair = bid * 8 + wip;            // 0 .. N_ARGS/2-1
        int a0 = pair * 2, a1 = a0 + 1;

        int r0 = arg_rel[a0],  r1 = arg_rel[a1];
        int e0 = arg_ent[a0],  e1 = arg_ent[a1];
        int t0 = arg_trig[a0], t1 = arg_trig[a1];
        int m0 = arg_is_in[a0], m1 = arg_is_in[a1];
        int rt0 = rtype_ids[r0], rt1 = rtype_ids[r1];

        // rel_embeds is a pure stream: evict_first so it doesn't thrash
        // ent_embeds / X atomic sectors out of L2.
        uint64_t pol;
        asm("createpolicy.fractional.L2::evict_first.b64 %0, 1.0;" : "=l"(pol));

        const float4* relv0 = (const float4*)(rel_embeds  + (size_t)r0  * REL_R);
        const float4* rtv0  = (const float4*)(rtype_table + (size_t)rt0 * RTYPE_DIM);
        const float4* entv0 = (const float4*)(ent_embeds  + (size_t)e0  * ENT_DIM);
        const float4* relv1 = (const float4*)(rel_embeds  + (size_t)r1  * REL_R);
        const float4* rtv1  = (const float4*)(rtype_table + (size_t)rt1 * RTYPE_DIM);
        const float4* entv1 = (const float4*)(ent_embeds  + (size_t)e1  * ENT_DIM);
        __half* base0 = g_Xh + (size_t)t0 * KDIM + (m0 ? 0 : ARG_DIM);
        __half* base1 = g_Xh + (size_t)t1 * KDIM + (m1 ? 0 : ARG_DIM);

        #pragma unroll
        for (int it = 0; it < 3; ++it) {
            int c = lane + it * 32;          // 8-float chunk (0..71)
            if (c >= 72) break;
            float4 u0, u1, w0, w1;
            if (c < 32) {
                u0 = ld4_stream(relv0 + c * 2, pol);
                w0 = ld4_stream(relv1 + c * 2, pol);
                u1 = ld4_stream(relv0 + c * 2 + 1, pol);
                w1 = ld4_stream(relv1 + c * 2 + 1, pol);
            } else if (c < 36) {
                u0 = rtv0[(c - 32) * 2];  u1 = rtv0[(c - 32) * 2 + 1];
                w0 = rtv1[(c - 32) * 2];  w1 = rtv1[(c - 32) * 2 + 1];
            } else {
                u0 = entv0[(c - 36) * 2]; u1 = entv0[(c - 36) * 2 + 1];
                w0 = entv1[(c - 36) * 2]; w1 = entv1[(c - 36) * 2 + 1];
            }
            __half2 h0 = __floats2half2_rn(u0.x, u0.y);
            __half2 h1 = __floats2half2_rn(u0.z, u0.w);
            __half2 h2 = __floats2half2_rn(u1.x, u1.y);
            __half2 h3 = __floats2half2_rn(u1.z, u1.w);
            red_h8(base0 + c * 8, *(uint32_t*)&h0, *(uint32_t*)&h1,
                   *(uint32_t*)&h2, *(uint32_t*)&h3);
            __half2 g0 = __floats2half2_rn(w0.x, w0.y);
            __half2 g1 = __floats2half2_rn(w0.z, w0.w);
            __half2 g2 = __floats2half2_rn(w1.x, w1.y);
            __half2 g3 = __floats2half2_rn(w1.z, w1.w);
            red_h8(base1 + c * 8, *(uint32_t*)&g0, *(uint32_t*)&g1,
                   *(uint32_t*)&g2, *(uint32_t*)&g3);
        }
        return;
    }
    bid -= PREP_SCAT;
    {
        int warp = bid * 8 + wip;
        const float4* src = (const float4*)(ent_embeds + (size_t)trig_ent_id[warp] * ENT_DIM);
        float4* dst = (float4*)(out + (size_t)warp * OUT_COLS);
        #pragma unroll
        for (int it = 0; it < 3; ++it) {
            int c = lane + it * 32;
            if (c < ENT_DIM / 4) dst[c] = src[c];
        }
    }
}

// ---------------------------------------------------------------------------
// mma.sync fp16 GEMM: out[:,288:544] = Xh[50000,1152] @ Wcat
// CTA: 128 threads (4 warps), tile 128m x 128n, warp tile 64x64.
// K-chunk 64, 3-stage cp.async pipeline, np-granular LDSM/MMA overlap.
// ks-order rotated per warp parity to de-phase LDSM bursts across the two
// warps sharing an SMSP. Rows padded to 144 B. grid n-major.
// ---------------------------------------------------------------------------
#define CHUNK  64
#define NCH    (KDIM / CHUNK)         // 18
#define ROWB   144
#define OFF_B  (128 * ROWB)           // 18432
#define STG_STRIDE (2 * 128 * ROWB)   // 36864
#define NSTAGE 3
#define GSMEM  (NSTAGE * STG_STRIDE)  // 110592

__global__ __launch_bounds__(128, 2)
void gemm_mma_kernel(float* __restrict__ out) {
    extern __shared__ char sm[];
    const uint32_t smb = smem_u32(sm);
    const int tid = threadIdx.x;
    const int lid = tid & 31;
    const int wid = tid >> 5;
    const int m0 = blockIdx.y * 128;
    const int n0 = blockIdx.x * 128;
    const int wm = (wid >> 1) * 64;        // warp m offset (0 or 64)
    const int wn = (wid & 1) * 64;         // warp n offset (0 or 64)
    const int g  = lid >> 2;               // 0..7
    const int kp = (lid & 3) * 2;          // 0,2,4,6
    const int ksrot = (wid & 1) << 1;      // 0 or 2: de-phase warp pairs

    float acc[4][8][4];                    // mf x nf x frag
    #pragma unroll
    for (int a = 0; a < 4; a++)
        #pragma unroll
        for (int b = 0; b < 8; b++)
            #pragma unroll
            for (int c = 0; c < 4; c++) acc[a][b][c] = 0.f;

    auto cpStage = [&](int c, int p) {
        uint32_t stg = smb + p * STG_STRIDE;
        #pragma unroll
        for (int u = 0; u < 8; u++) {
            int idx = u * 128 + tid;         // 0..1023
            int row = idx >> 3, seg = idx & 7;
            int gm = m0 + row;
            const __half* sa = g_Xh + (size_t)gm * KDIM + c * CHUNK + seg * 8;
            cp16_pred(stg + row * ROWB + seg * 16, sa, (gm < N_TRIG) ? 16 : 0);
            const __half* sb = g_Bth + (size_t)(n0 + row) * KDIM + c * CHUNK + seg * 8;
            cp16(stg + OFF_B + row * ROWB + seg * 16, sb);
        }
        cp_commit();
    };

    auto compute = [&](int p) {
        const uint32_t base = smb + p * STG_STRIDE;
        #pragma unroll
        for (int kk = 0; kk < 4; kk++) {
            const int ks = (kk + ksrot) & 3;   // rotated walk per warp parity
            uint32_t a[4][4], b[4][4];
            // earliest-needed loads first: b[0], then A; rest of B overlaps MMAs
            {
                uint32_t addr = base + OFF_B + (uint32_t)(wn + (lid & 15)) * ROWB
                              + ks * 32 + (lid >> 4) * 16;
                LDMATRIX_X4(b[0], addr);
            }
            #pragma unroll
            for (int mf = 0; mf < 4; mf++) {
                uint32_t addr = base + (uint32_t)(wm + mf * 16 + (lid & 15)) * ROWB
                              + ks * 32 + (lid >> 4) * 16;
                LDMATRIX_X4(a[mf], addr);
            }
            #pragma unroll
            for (int np = 0; np < 4; np++) {
                if (np < 3) {
                    uint32_t addr = base + OFF_B
                                  + (uint32_t)(wn + (np + 1) * 16 + (lid & 15)) * ROWB
                                  + ks * 32 + (lid >> 4) * 16;
                    LDMATRIX_X4(b[np + 1], addr);
                }
                uint32_t blo[2] = { b[np][0], b[np][2] };
                uint32_t bhi[2] = { b[np][1], b[np][3] };
                #pragma unroll
                for (int mf = 0; mf < 4; mf++) {
                    MMA_F16(acc[mf][2 * np],     a[mf], blo);
                    MMA_F16(acc[mf][2 * np + 1], a[mf], bhi);
                }
            }
        }
    };

    // ---- prologue: stages 0,1 in flight ----
    cpStage(0, 0);
    cpStage(1, 1);

    // ---- mainloop (single sync per iteration; 3 stages make the write
    //      target (i+2)%3 == (i-1)%3, protected by this sync) ----
    for (int i = 0; i < NCH; i++) {
        cp_wait<1>();
        __syncthreads();
        if (i + 2 < NCH) cpStage(i + 2, (i + 2) % NSTAGE);
        else             cp_commit();           // keep group count uniform
        compute(i % NSTAGE);
    }

    // ---- epilogue ----
    #pragma unroll
    for (int mf = 0; mf < 4; mf++) {
        int r = m0 + wm + mf * 16 + g;
        #pragma unroll
        for (int nf = 0; nf < 8; nf++) {
            int cc = ENT_DIM + n0 + wn + nf * 8 + kp;
            if (r < N_TRIG)
                *(float2*)(out + (size_t)r * OUT_COLS + cc) =
                    make_float2(acc[mf][nf][0], acc[mf][nf][1]);
            if (r + 8 < N_TRIG)
                *(float2*)(out + (size_t)(r + 8) * OUT_COLS + cc) =
                    make_float2(acc[mf][nf][2], acc[mf][nf][3]);
        }
    }
}

// ---------------------------------------------------------------------------
// Launch
// ---------------------------------------------------------------------------
extern "C" void kernel_launch(void* const* d_in, const int* in_sizes, int n_in,
                              void* d_out, int out_size) {
    const float* ent_embeds  = (const float*)d_in[0];
    const float* rel_embeds  = (const float*)d_in[1];
    const float* rtype_table = (const float*)d_in[2];
    const float* W_in        = (const float*)d_in[3];
    const float* W_out       = (const float*)d_in[4];
    const int*   rtype_ids   = (const int*)d_in[5];
    const int*   trig_ent_id = (const int*)d_in[6];
    const int*   arg_trig    = (const int*)d_in[7];
    const int*   arg_rel     = (const int*)d_in[8];
    const int*   arg_ent     = (const int*)d_in[9];
    const int*   arg_is_in   = (const int*)d_in[10];
    float* out = (float*)d_out;

    cudaFuncSetAttribute(gemm_mma_kernel,
                         cudaFuncAttributeMaxDynamicSharedMemorySize, GSMEM);

    // zero fp16 X accumulator (115 MB)
    void* xptr = nullptr;
    cudaGetSymbolAddress(&xptr, g_Xh);
    cudaMemsetAsync(xptr, 0, (size_t)N_TRIG * KDIM * sizeof(__half), 0);

    // fused: W transpose + scatter + trigger-embedding copy
    prep_kernel<<<PREP_GRID, 256>>>(ent_embeds, rel_embeds, rtype_table,
                                    W_in, W_out, rtype_ids, trig_ent_id,
                                    arg_trig, arg_rel, arg_ent, arg_is_in, out);

    // tensor-core GEMM -> out[:, 288:544]
    dim3 grid(ROLE_DIM / 128, (N_TRIG + 127) / 128);
    gemm_mma_kernel<<<grid, 128, GSMEM>>>(out);
}